// round 7
// baseline (speedup 1.0000x reference)
#include <cuda_runtime.h>
#include <cuda_bf16.h>
#include <math.h>
#include <stdint.h>

// Problem constants (fixed shapes per reference)
#define NN   50000
#define EE   800000
#define GG   64
#define HH   4
#define HDIM 256   // 4 heads * 64
#define NB_SCAN ((NN + 1023) / 1024)

// ---------------- scratch (static device memory; no allocs) ----------------
__device__ __align__(16) float g_xl[NN * HDIM];
__device__ __align__(16) float g_xr[NN * HDIM];
__device__ __align__(16) float g_h2[NN * HDIM];
__device__ __align__(16) float g_cnt[GG];
__device__ __align__(16) __nv_bfloat16 g_ahi[NN * HDIM];   // A operand hi (x split, then h1 split)
__device__ __align__(16) __nv_bfloat16 g_alo[NN * HDIM];   // A operand lo
__device__ __align__(16) __nv_bfloat16 g_whi[196608];      // Wl1|Wr1|Wl2|Wr2 hi
__device__ __align__(16) __nv_bfloat16 g_wlo[196608];      // lo
__device__ int g_deg[NN];
__device__ int g_fill[NN];
__device__ int g_rowptr[NN + 1];
__device__ int g_col[EE];
__device__ int g_partial[NB_SCAN];

// W offsets inside g_whi/g_wlo (elements)
#define WOFF_L1 0
#define WOFF_R1 32768
#define WOFF_L2 65536
#define WOFF_R2 131072

// ================= bf16 helpers =================
static __device__ __forceinline__ uint32_t smem_u32(const void* p) {
    uint32_t a;
    asm("{ .reg .u64 t; cvta.to.shared.u64 t, %1; cvt.u32.u64 %0, t; }"
        : "=r"(a) : "l"(p));
    return a;
}
static __device__ __forceinline__ unsigned short bf_us(float x) {
    __nv_bfloat16 h = __float2bfloat16_rn(x);
    return *(unsigned short*)&h;
}
static __device__ __forceinline__ float bf_f(unsigned short u) {
    __nv_bfloat16 h = *(__nv_bfloat16*)&u;
    return __bfloat162float(h);
}
static __device__ __forceinline__ void cvt_hilo(float4 v, uint2& hi, uint2& lo) {
    unsigned short h0 = bf_us(v.x), h1 = bf_us(v.y), h2 = bf_us(v.z), h3 = bf_us(v.w);
    unsigned short l0 = bf_us(v.x - bf_f(h0));
    unsigned short l1 = bf_us(v.y - bf_f(h1));
    unsigned short l2 = bf_us(v.z - bf_f(h2));
    unsigned short l3 = bf_us(v.w - bf_f(h3));
    hi.x = (uint32_t)h0 | ((uint32_t)h1 << 16);
    hi.y = (uint32_t)h2 | ((uint32_t)h3 << 16);
    lo.x = (uint32_t)l0 | ((uint32_t)l1 << 16);
    lo.y = (uint32_t)l2 | ((uint32_t)l3 << 16);
}
static __device__ __forceinline__ void ldsm4(uint32_t addr, uint32_t* r) {
    asm volatile("ldmatrix.sync.aligned.m8n8.x4.shared.b16 {%0,%1,%2,%3}, [%4];"
                 : "=r"(r[0]), "=r"(r[1]), "=r"(r[2]), "=r"(r[3]) : "r"(addr));
}
static __device__ __forceinline__ void ldsm4t(uint32_t addr, uint32_t* r) {
    asm volatile("ldmatrix.sync.aligned.m8n8.x4.trans.shared.b16 {%0,%1,%2,%3}, [%4];"
                 : "=r"(r[0]), "=r"(r[1]), "=r"(r[2]), "=r"(r[3]) : "r"(addr));
}
static __device__ __forceinline__ void mma_bf16(float* d, const uint32_t* a,
                                                uint32_t b0, uint32_t b1) {
    asm volatile(
        "mma.sync.aligned.m16n8k16.row.col.f32.bf16.bf16.f32 "
        "{%0,%1,%2,%3}, {%4,%5,%6,%7}, {%8,%9}, {%0,%1,%2,%3};"
        : "+f"(d[0]), "+f"(d[1]), "+f"(d[2]), "+f"(d[3])
        : "r"(a[0]), "r"(a[1]), "r"(a[2]), "r"(a[3]), "r"(b0), "r"(b1));
}
static __device__ __forceinline__ void cpasync16(uint32_t s, const void* g, int sz) {
    asm volatile("cp.async.ca.shared.global [%0], [%1], 16, %2;"
                 :: "r"(s), "l"(g), "r"(sz) : "memory");
}

// ================= pre-split kernels =================
__global__ void split_kernel(const float* __restrict__ src,
                             __nv_bfloat16* __restrict__ hi,
                             __nv_bfloat16* __restrict__ lo, int n4) {
    int i = blockIdx.x * blockDim.x + threadIdx.x;
    if (i >= n4) return;
    float4 v = ((const float4*)src)[i];
    uint2 h, l;
    cvt_hilo(v, h, l);
    ((uint2*)hi)[i] = h;
    ((uint2*)lo)[i] = l;
}

// ================= bf16 3-pass mma.sync GEMM (cp.async pipelined) =================
// Block 128x128, BK=32, 8 warps (m32 x n64 each), 2-stage double buffer.
// Per-stage smem: A hi/lo 128 rows x 32 bf16 (stride 80B), B hi/lo 32 x 128 (stride 272B).
#define ASTR 80
#define BSTR 272
#define SA_HI 0
#define SA_LO 10240
#define SB_HI 20480
#define SB_LO 29184
#define STAGE_SZ 37888
#define SM_GEMM_TOT (2 * STAGE_SZ)   // 75776 bytes dynamic

static __device__ __forceinline__ void fill_tile(
    uint32_t smb, int stg, int t,
    const __nv_bfloat16* __restrict__ ahi, const __nv_bfloat16* __restrict__ alo,
    const __nv_bfloat16* __restrict__ whi, const __nv_bfloat16* __restrict__ wlo,
    int rowBase, int colW, int k0, int M, int K) {
    const uint32_t sb = smb + stg * STAGE_SZ;
    // A: 512 16B slots per array
    #pragma unroll
    for (int i = 0; i < 2; i++) {
        const int s   = t + i * 256;
        const int row = s >> 2;
        const int kq  = s & 3;
        const int gr  = rowBase + row;
        const int ok  = (gr < M) ? 16 : 0;
        const int grc = (gr < M) ? gr : 0;
        const size_t eoff = (size_t)grc * K + k0 + kq * 8;
        const uint32_t so = sb + SA_HI + row * ASTR + kq * 16;
        cpasync16(so, ahi + eoff, ok);
        cpasync16(so + (SA_LO - SA_HI), alo + eoff, ok);
    }
    // B: 512 16B slots per array
    #pragma unroll
    for (int i = 0; i < 2; i++) {
        const int s   = t + i * 256;
        const int row = s >> 4;
        const int c8  = s & 15;
        const size_t eoff = (size_t)(k0 + row) * HDIM + colW + c8 * 8;
        const uint32_t so = sb + SB_HI + row * BSTR + c8 * 16;
        cpasync16(so, whi + eoff, 16);
        cpasync16(so + (SB_LO - SB_HI), wlo + eoff, 16);
    }
}

// blockIdx.x: 0,1 -> W0 cols 0-127 / 128-255 ; 2,3 -> W1
__global__ void __launch_bounds__(256)
gemm_mma_kernel(const __nv_bfloat16* __restrict__ ahi,
                const __nv_bfloat16* __restrict__ alo,
                const __nv_bfloat16* __restrict__ w0hi,
                const __nv_bfloat16* __restrict__ w0lo,
                const __nv_bfloat16* __restrict__ w1hi,
                const __nv_bfloat16* __restrict__ w1lo,
                const float* __restrict__ b0, const float* __restrict__ b1,
                float* __restrict__ C0, float* __restrict__ C1,
                int M, int K) {
    extern __shared__ __align__(16) unsigned char smbuf[];
    const uint32_t smb = smem_u32(smbuf);

    const int t    = threadIdx.x;
    const int lane = t & 31;
    const int wid  = t >> 5;
    const int wm   = wid & 3;
    const int wn   = wid >> 2;
    const int rowBase = blockIdx.y * 128;
    const int colW    = (blockIdx.x & 1) * 128;

    const __nv_bfloat16* __restrict__ whi = (blockIdx.x < 2) ? w0hi : w1hi;
    const __nv_bfloat16* __restrict__ wlo = (blockIdx.x < 2) ? w0lo : w1lo;
    const float* __restrict__ bias        = (blockIdx.x < 2) ? b0 : b1;
    float* __restrict__ C                 = (blockIdx.x < 2) ? C0 : C1;

    float acc[2][8][4];
    #pragma unroll
    for (int i = 0; i < 2; i++)
        #pragma unroll
        for (int j = 0; j < 8; j++)
            #pragma unroll
            for (int q = 0; q < 4; q++) acc[i][j][q] = 0.0f;

    const int niter = K >> 5;

    fill_tile(smb, 0, t, ahi, alo, whi, wlo, rowBase, colW, 0, M, K);
    asm volatile("cp.async.commit_group;" ::: "memory");

    for (int kc = 0; kc < niter; kc++) {
        if (kc + 1 < niter) {
            fill_tile(smb, (kc + 1) & 1, t, ahi, alo, whi, wlo,
                      rowBase, colW, (kc + 1) << 5, M, K);
            asm volatile("cp.async.commit_group;" ::: "memory");
            asm volatile("cp.async.wait_group 1;" ::: "memory");
        } else {
            asm volatile("cp.async.wait_group 0;" ::: "memory");
        }
        __syncthreads();

        const uint32_t sb = smb + (kc & 1) * STAGE_SZ;
        #pragma unroll
        for (int s = 0; s < 2; s++) {
            uint32_t av_hi[2][4], av_lo[2][4];
            #pragma unroll
            for (int mt = 0; mt < 2; mt++) {
                const int row = wm * 32 + mt * 16 + (lane & 15);
                const uint32_t aoff = row * ASTR + (lane >> 4) * 16 + s * 32;
                ldsm4(sb + SA_HI + aoff, av_hi[mt]);
                ldsm4(sb + SA_LO + aoff, av_lo[mt]);
            }
            #pragma unroll
            for (int np = 0; np < 4; np++) {
                const int g    = lane >> 3;
                const int krow = s * 16 + (g & 1) * 8 + (lane & 7);
                const int ncol = wn * 64 + np * 16 + (g >> 1) * 8;
                const uint32_t boff = krow * BSTR + ncol * 2;
                uint32_t bhi[4], blo[4];
                ldsm4t(sb + SB_HI + boff, bhi);
                ldsm4t(sb + SB_LO + boff, blo);
                #pragma unroll
                for (int mt = 0; mt < 2; mt++) {
                    #pragma unroll
                    for (int tt = 0; tt < 2; tt++) {
                        float* d = acc[mt][np * 2 + tt];
                        mma_bf16(d, av_hi[mt], bhi[2 * tt], bhi[2 * tt + 1]);
                        mma_bf16(d, av_hi[mt], blo[2 * tt], blo[2 * tt + 1]);
                        mma_bf16(d, av_lo[mt], bhi[2 * tt], bhi[2 * tt + 1]);
                    }
                }
            }
        }
        __syncthreads();
    }

    // ---- epilogue: acc + bias -> C ----
    #pragma unroll
    for (int mt = 0; mt < 2; mt++) {
        const int r0 = rowBase + wm * 32 + mt * 16 + (lane >> 2);
        #pragma unroll
        for (int nt = 0; nt < 8; nt++) {
            const int cg = colW + wn * 64 + nt * 8 + (lane & 3) * 2;
            const float2 bv = __ldg((const float2*)&bias[cg]);
            if (r0 < M) {
                float2 v = make_float2(acc[mt][nt][0] + bv.x, acc[mt][nt][1] + bv.y);
                *(float2*)&C[(size_t)r0 * HDIM + cg] = v;
            }
            if (r0 + 8 < M) {
                float2 v = make_float2(acc[mt][nt][2] + bv.x, acc[mt][nt][3] + bv.y);
                *(float2*)&C[(size_t)(r0 + 8) * HDIM + cg] = v;
            }
        }
    }
}

// ---------------- CSR build ----------------
__global__ void deg_kernel(const int* __restrict__ ei, int* __restrict__ deg) {
    int e = blockIdx.x * blockDim.x + threadIdx.x;
    if (e < EE) atomicAdd(&deg[ei[EE + e]], 1);
}

__global__ void scan_block_kernel(const int* __restrict__ deg,
                                  int* __restrict__ excl,
                                  int* __restrict__ partial) {
    __shared__ int tsum[256];
    const int base = blockIdx.x * 1024;
    const int idx0 = base + threadIdx.x * 4;
    int v[4], pre[4];
    #pragma unroll
    for (int j = 0; j < 4; j++) v[j] = (idx0 + j < NN) ? deg[idx0 + j] : 0;
    int run = 0;
    #pragma unroll
    for (int j = 0; j < 4; j++) { pre[j] = run; run += v[j]; }
    tsum[threadIdx.x] = run;
    __syncthreads();
    #pragma unroll
    for (int off = 1; off < 256; off <<= 1) {
        int tv = (threadIdx.x >= off) ? tsum[threadIdx.x - off] : 0;
        __syncthreads();
        tsum[threadIdx.x] += tv;
        __syncthreads();
    }
    const int tOff = (threadIdx.x > 0) ? tsum[threadIdx.x - 1] : 0;
    #pragma unroll
    for (int j = 0; j < 4; j++)
        if (idx0 + j < NN) excl[idx0 + j] = tOff + pre[j];
    if (threadIdx.x == 255) partial[blockIdx.x] = tsum[255];
}

__global__ void scan_partial_kernel(int* __restrict__ partial) {
    if (threadIdx.x == 0) {
        int run = 0;
        for (int i = 0; i < NB_SCAN; i++) { int t = partial[i]; partial[i] = run; run += t; }
    }
}

__global__ void add_offset_kernel(int* __restrict__ rowptr, const int* __restrict__ partial) {
    int i = blockIdx.x * blockDim.x + threadIdx.x;
    if (i < NN) rowptr[i] += partial[i >> 10];
    if (i == 0) rowptr[NN] = EE;
}

__global__ void scatter_kernel(const int* __restrict__ ei,
                               const int* __restrict__ rowptr,
                               int* __restrict__ fill,
                               int* __restrict__ col) {
    int e = blockIdx.x * blockDim.x + threadIdx.x;
    if (e >= EE) return;
    const int dst = ei[EE + e];
    const int p = atomicAdd(&fill[dst], 1);
    col[rowptr[dst] + p] = ei[e];
}

// ---------------- node-major fused GATv2 aggregation ----------------
// SPLIT=true: output packed bf16 hi/lo (identical values to a later split of
// the fp32 result). SPLIT=false: output fp32.
template <bool SILU, bool SPLIT>
__global__ void node_aggr_kernel(const int* __restrict__ rowptr,
                                 const int* __restrict__ col,
                                 const float* __restrict__ xl,
                                 const float* __restrict__ xr,
                                 const float* __restrict__ att,
                                 const float* __restrict__ bias,
                                 float* __restrict__ hout,
                                 __nv_bfloat16* __restrict__ hhi,
                                 __nv_bfloat16* __restrict__ hlo) {
    const int node = (blockIdx.x * blockDim.x + threadIdx.x) >> 5;
    const int lane = threadIdx.x & 31;
    if (node >= NN) return;

    const float4* __restrict__ xd = (const float4*)(xr + (size_t)node * HDIM);
    const float4 r0 = xd[lane];
    const float4 r1 = xd[lane + 32];
    const float4 a0 = __ldg(&((const float4*)att)[lane]);
    const float4 a1 = __ldg(&((const float4*)att)[lane + 32]);

    float4 acc0 = make_float4(0.f, 0.f, 0.f, 0.f);
    float4 acc1 = make_float4(0.f, 0.f, 0.f, 0.f);
    float denL = 0.f, denH = 0.f;

    const int pBeg = rowptr[node];
    const int pEnd = rowptr[node + 1];

    float4 l0n, l1n;
    if (pBeg < pEnd) {
        const float4* xs = (const float4*)(xl + (size_t)col[pBeg] * HDIM);
        l0n = xs[lane];
        l1n = xs[lane + 32];
    }

    for (int p = pBeg; p < pEnd; p++) {
        const float4 l0 = l0n;
        const float4 l1 = l1n;
        if (p + 1 < pEnd) {
            const float4* xs = (const float4*)(xl + (size_t)col[p + 1] * HDIM);
            l0n = xs[lane];
            l1n = xs[lane + 32];
        }

        float4 s0, s1;
        s0.x = l0.x + r0.x; s0.y = l0.y + r0.y; s0.z = l0.z + r0.z; s0.w = l0.w + r0.w;
        s1.x = l1.x + r1.x; s1.y = l1.y + r1.y; s1.z = l1.z + r1.z; s1.w = l1.w + r1.w;
        s0.x = s0.x > 0.f ? s0.x : 0.2f * s0.x;
        s0.y = s0.y > 0.f ? s0.y : 0.2f * s0.y;
        s0.z = s0.z > 0.f ? s0.z : 0.2f * s0.z;
        s0.w = s0.w > 0.f ? s0.w : 0.2f * s0.w;
        s1.x = s1.x > 0.f ? s1.x : 0.2f * s1.x;
        s1.y = s1.y > 0.f ? s1.y : 0.2f * s1.y;
        s1.z = s1.z > 0.f ? s1.z : 0.2f * s1.z;
        s1.w = s1.w > 0.f ? s1.w : 0.2f * s1.w;

        float p0 = s0.x * a0.x + s0.y * a0.y + s0.z * a0.z + s0.w * a0.w;
        float p1 = s1.x * a1.x + s1.y * a1.y + s1.z * a1.z + s1.w * a1.w;
        #pragma unroll
        for (int o = 8; o > 0; o >>= 1) {
            p0 += __shfl_xor_sync(0xFFFFFFFFu, p0, o);
            p1 += __shfl_xor_sync(0xFFFFFFFFu, p1, o);
        }
        const float eL = __expf(p0);
        const float eH = __expf(p1);

        acc0.x = fmaf(l0.x, eL, acc0.x); acc0.y = fmaf(l0.y, eL, acc0.y);
        acc0.z = fmaf(l0.z, eL, acc0.z); acc0.w = fmaf(l0.w, eL, acc0.w);
        acc1.x = fmaf(l1.x, eH, acc1.x); acc1.y = fmaf(l1.y, eH, acc1.y);
        acc1.z = fmaf(l1.z, eH, acc1.z); acc1.w = fmaf(l1.w, eH, acc1.w);
        denL += eL;
        denH += eH;
    }

    const float invL = 1.0f / (denL + 1e-16f);
    const float invH = 1.0f / (denH + 1e-16f);
    const float4 b0 = __ldg(&((const float4*)bias)[lane]);
    const float4 b1 = __ldg(&((const float4*)bias)[lane + 32]);

    float4 o0, o1;
    o0.x = acc0.x * invL + b0.x; o0.y = acc0.y * invL + b0.y;
    o0.z = acc0.z * invL + b0.z; o0.w = acc0.w * invL + b0.w;
    o1.x = acc1.x * invH + b1.x; o1.y = acc1.y * invH + b1.y;
    o1.z = acc1.z * invH + b1.z; o1.w = acc1.w * invH + b1.w;
    if (SILU) {
        o0.x = o0.x / (1.0f + __expf(-o0.x));
        o0.y = o0.y / (1.0f + __expf(-o0.y));
        o0.z = o0.z / (1.0f + __expf(-o0.z));
        o0.w = o0.w / (1.0f + __expf(-o0.w));
        o1.x = o1.x / (1.0f + __expf(-o1.x));
        o1.y = o1.y / (1.0f + __expf(-o1.y));
        o1.z = o1.z / (1.0f + __expf(-o1.z));
        o1.w = o1.w / (1.0f + __expf(-o1.w));
    }
    if (SPLIT) {
        uint2 h0, l0v, h1, l1v;
        cvt_hilo(o0, h0, l0v);
        cvt_hilo(o1, h1, l1v);
        const size_t base = (size_t)node * HDIM;
        ((uint2*)(hhi + base))[lane]      = h0;
        ((uint2*)(hlo + base))[lane]      = l0v;
        ((uint2*)(hhi + base))[lane + 32] = h1;
        ((uint2*)(hlo + base))[lane + 32] = l1v;
    } else {
        float4* ho = (float4*)(hout + (size_t)node * HDIM);
        ho[lane]      = o0;
        ho[lane + 32] = o1;
    }
}

// ---------------- global mean pool ----------------
__global__ void pool_acc_kernel(const float* __restrict__ h,
                                const int* __restrict__ batch,
                                float* __restrict__ out,
                                float* __restrict__ cnt) {
    int i = blockIdx.x * blockDim.x + threadIdx.x;
    if (i >= NN * 64) return;
    const int n  = i >> 6;
    const int c4 = i & 63;
    const int b  = batch[n];
    float4 v = ((const float4*)(h + (size_t)n * HDIM))[c4];
    atomicAdd(&((float4*)(out + (size_t)b * HDIM))[c4], v);
    if (c4 == 0) atomicAdd(&cnt[b], 1.0f);
}

__global__ void pool_div_kernel(float* __restrict__ out, const float* __restrict__ cnt) {
    int i = blockIdx.x * blockDim.x + threadIdx.x;
    if (i < GG * HDIM) out[i] = out[i] / fmaxf(cnt[i >> 8], 1.0f);
}

// ---------------- launch ----------------
extern "C" void kernel_launch(void* const* d_in, const int* in_sizes, int n_in,
                              void* d_out, int out_size) {
    const float* x     = (const float*)d_in[0];
    const int*   ei    = (const int*)  d_in[1];
    const int*   batch = (const int*)  d_in[2];
    const float* Wl1   = (const float*)d_in[3];
    const float* bl1   = (const float*)d_in[4];
    const float* Wr1   = (const float*)d_in[5];
    const float* br1   = (const float*)d_in[6];
    const float* att1  = (const float*)d_in[7];
    const float* bias1 = (const float*)d_in[8];
    const float* Wl2   = (const float*)d_in[9];
    const float* bl2   = (const float*)d_in[10];
    const float* Wr2   = (const float*)d_in[11];
    const float* br2   = (const float*)d_in[12];
    const float* att2  = (const float*)d_in[13];
    const float* bias2 = (const float*)d_in[14];
    float* out = (float*)d_out;

    float *xl, *xr, *h2, *cnt;
    __nv_bfloat16 *ahi, *alo, *whi, *wlo;
    int *deg, *fill, *rowptr, *colA, *partial;
    cudaGetSymbolAddress((void**)&xl,      g_xl);
    cudaGetSymbolAddress((void**)&xr,      g_xr);
    cudaGetSymbolAddress((void**)&h2,      g_h2);
    cudaGetSymbolAddress((void**)&cnt,     g_cnt);
    cudaGetSymbolAddress((void**)&ahi,     g_ahi);
    cudaGetSymbolAddress((void**)&alo,     g_alo);
    cudaGetSymbolAddress((void**)&whi,     g_whi);
    cudaGetSymbolAddress((void**)&wlo,     g_wlo);
    cudaGetSymbolAddress((void**)&deg,     g_deg);
    cudaGetSymbolAddress((void**)&fill,    g_fill);
    cudaGetSymbolAddress((void**)&rowptr,  g_rowptr);
    cudaGetSymbolAddress((void**)&colA,    g_col);
    cudaGetSymbolAddress((void**)&partial, g_partial);

    cudaFuncSetAttribute(gemm_mma_kernel,
                         cudaFuncAttributeMaxDynamicSharedMemorySize, SM_GEMM_TOT);

    const dim3 ggrid(4, (NN + 127) / 128);
    const int nb4 = (NN * 64 + 255) / 256;
    const int ebE = (EE + 255) / 256;
    const int nwb = (NN * 32 + 255) / 256;

    // ---- pre-split operands to bf16 hi/lo ----
    split_kernel<<<(NN * 128 / 4 + 255) / 256, 256>>>(x, ahi, alo, NN * 128 / 4);
    split_kernel<<<(32768 / 4 + 255) / 256, 256>>>(Wl1, whi + WOFF_L1, wlo + WOFF_L1, 32768 / 4);
    split_kernel<<<(32768 / 4 + 255) / 256, 256>>>(Wr1, whi + WOFF_R1, wlo + WOFF_R1, 32768 / 4);
    split_kernel<<<(65536 / 4 + 255) / 256, 256>>>(Wl2, whi + WOFF_L2, wlo + WOFF_L2, 65536 / 4);
    split_kernel<<<(65536 / 4 + 255) / 256, 256>>>(Wr2, whi + WOFF_R2, wlo + WOFF_R2, 65536 / 4);

    // ---- CSR build (used by both layers) ----
    cudaMemsetAsync(deg, 0, NN * sizeof(int));
    cudaMemsetAsync(fill, 0, NN * sizeof(int));
    deg_kernel<<<ebE, 256>>>(ei, deg);
    scan_block_kernel<<<NB_SCAN, 256>>>(deg, rowptr, partial);
    scan_partial_kernel<<<1, 32>>>(partial);
    add_offset_kernel<<<(NN + 255) / 256, 256>>>(rowptr, partial);
    scatter_kernel<<<ebE, 256>>>(ei, rowptr, fill, colA);

    // ---- layer 1 ----
    gemm_mma_kernel<<<ggrid, 256, SM_GEMM_TOT>>>(
        ahi, alo, whi + WOFF_L1, wlo + WOFF_L1, whi + WOFF_R1, wlo + WOFF_R1,
        bl1, br1, xl, xr, NN, 128);
    node_aggr_kernel<true, true><<<nwb, 256>>>(rowptr, colA, xl, xr, att1, bias1,
                                               nullptr, ahi, alo);

    // ---- layer 2 (A = h1 hi/lo written by node_aggr) ----
    gemm_mma_kernel<<<ggrid, 256, SM_GEMM_TOT>>>(
        ahi, alo, whi + WOFF_L2, wlo + WOFF_L2, whi + WOFF_R2, wlo + WOFF_R2,
        bl2, br2, xl, xr, NN, 256);
    node_aggr_kernel<false, false><<<nwb, 256>>>(rowptr, colA, xl, xr, att2, bias2,
                                                 h2, nullptr, nullptr);

    // ---- global mean pool ----
    cudaMemsetAsync(out, 0, (size_t)GG * HDIM * sizeof(float));
    cudaMemsetAsync(cnt, 0, (size_t)GG * sizeof(float));
    pool_acc_kernel<<<nb4, 256>>>(h2, batch, out, cnt);
    pool_div_kernel<<<(GG * HDIM + 255) / 256, 256>>>(out, cnt);
}

// round 8
// speedup vs baseline: 1.0389x; 1.0389x over previous
#include <cuda_runtime.h>
#include <cuda_bf16.h>
#include <math.h>
#include <stdint.h>

// Problem constants (fixed shapes per reference)
#define NN   50000
#define EE   800000
#define GG   64
#define HH   4
#define HDIM 256   // 4 heads * 64
#define NB_SCAN ((NN + 1023) / 1024)

// ---------------- scratch (static device memory; no allocs) ----------------
__device__ __align__(16) float g_xl[NN * HDIM];
__device__ __align__(16) float g_xr[NN * HDIM];
__device__ __align__(16) float g_h1[NN * HDIM];
__device__ __align__(16) float g_h2[NN * HDIM];
__device__ __align__(16) float g_cnt[GG];
__device__ int g_deg[NN];
__device__ int g_fill[NN];
__device__ int g_rowptr[NN + 1];
__device__ int g_col[EE];
__device__ int g_partial[NB_SCAN];

// ================= bf16 3-pass mma.sync GEMM =================
// Block tile 128x128, BK=32, 8 warps (warp tile m32 x n64).
// smem: A_hi/A_lo 128 rows x 32 bf16 (stride 80B), B_hi/B_lo 32 x 128 (stride 272B).
#define ASTR 80
#define BSTR 272
#define OFF_AHI 0
#define OFF_ALO (128 * ASTR)                   // 10240
#define OFF_BHI (2 * 128 * ASTR)               // 20480
#define OFF_BLO (2 * 128 * ASTR + 32 * BSTR)   // 29184
#define SM_GEMM (2 * 128 * ASTR + 2 * 32 * BSTR)   // 37888 bytes

static __device__ __forceinline__ uint32_t smem_u32(const void* p) {
    uint32_t a;
    asm("{ .reg .u64 t; cvta.to.shared.u64 t, %1; cvt.u32.u64 %0, t; }"
        : "=r"(a) : "l"(p));
    return a;
}
static __device__ __forceinline__ unsigned short bf_us(float x) {
    __nv_bfloat16 h = __float2bfloat16_rn(x);
    return *(unsigned short*)&h;
}
static __device__ __forceinline__ float bf_f(unsigned short u) {
    __nv_bfloat16 h = *(__nv_bfloat16*)&u;
    return __bfloat162float(h);
}
static __device__ __forceinline__ void cvt_hilo(float4 v, uint2& hi, uint2& lo) {
    unsigned short h0 = bf_us(v.x), h1 = bf_us(v.y), h2 = bf_us(v.z), h3 = bf_us(v.w);
    unsigned short l0 = bf_us(v.x - bf_f(h0));
    unsigned short l1 = bf_us(v.y - bf_f(h1));
    unsigned short l2 = bf_us(v.z - bf_f(h2));
    unsigned short l3 = bf_us(v.w - bf_f(h3));
    hi.x = (uint32_t)h0 | ((uint32_t)h1 << 16);
    hi.y = (uint32_t)h2 | ((uint32_t)h3 << 16);
    lo.x = (uint32_t)l0 | ((uint32_t)l1 << 16);
    lo.y = (uint32_t)l2 | ((uint32_t)l3 << 16);
}
static __device__ __forceinline__ void ldsm4(uint32_t addr, uint32_t* r) {
    asm volatile("ldmatrix.sync.aligned.m8n8.x4.shared.b16 {%0,%1,%2,%3}, [%4];"
                 : "=r"(r[0]), "=r"(r[1]), "=r"(r[2]), "=r"(r[3]) : "r"(addr));
}
static __device__ __forceinline__ void ldsm4t(uint32_t addr, uint32_t* r) {
    asm volatile("ldmatrix.sync.aligned.m8n8.x4.trans.shared.b16 {%0,%1,%2,%3}, [%4];"
                 : "=r"(r[0]), "=r"(r[1]), "=r"(r[2]), "=r"(r[3]) : "r"(addr));
}
static __device__ __forceinline__ void mma_bf16(float* d, const uint32_t* a,
                                                uint32_t b0, uint32_t b1) {
    asm volatile(
        "mma.sync.aligned.m16n8k16.row.col.f32.bf16.bf16.f32 "
        "{%0,%1,%2,%3}, {%4,%5,%6,%7}, {%8,%9}, {%0,%1,%2,%3};"
        : "+f"(d[0]), "+f"(d[1]), "+f"(d[2]), "+f"(d[3])
        : "r"(a[0]), "r"(a[1]), "r"(a[2]), "r"(a[3]), "r"(b0), "r"(b1));
}

// C0 = A@W0 + b0 (blockIdx.x<2) / C1 = A@W1 + b1 ; colBase=(x&1)*128
__global__ void __launch_bounds__(256, 2)
gemm_mma_kernel(const float* __restrict__ A,
                const float* __restrict__ W0, const float* __restrict__ W1,
                const float* __restrict__ b0, const float* __restrict__ b1,
                float* __restrict__ C0, float* __restrict__ C1,
                int M, int K) {
    __shared__ __align__(16) unsigned char smbuf[SM_GEMM];
    const uint32_t smb = smem_u32(smbuf);

    const int t    = threadIdx.x;
    const int lane = t & 31;
    const int wid  = t >> 5;
    const int wm   = wid & 3;          // 4 warps over M (32 rows each)
    const int wn   = wid >> 2;         // 2 warps over N (64 cols each)
    const int rowBase = blockIdx.y * 128;
    const int colW    = (blockIdx.x & 1) * 128;

    const float* __restrict__ Wm   = (blockIdx.x < 2) ? W0 : W1;
    const float* __restrict__ bias = (blockIdx.x < 2) ? b0 : b1;
    float* __restrict__ C          = (blockIdx.x < 2) ? C0 : C1;

    float acc[2][8][4];
    #pragma unroll
    for (int i = 0; i < 2; i++)
        #pragma unroll
        for (int j = 0; j < 8; j++)
            #pragma unroll
            for (int q = 0; q < 4; q++) acc[i][j][q] = 0.0f;

    for (int k0 = 0; k0 < K; k0 += 32) {
        // ---- fill A: 128 rows x 32 k (1024 float4 slots) ----
        #pragma unroll
        for (int i = 0; i < 4; i++) {
            const int slot = t + i * 256;
            const int row  = slot >> 3;
            const int kq   = slot & 7;
            const int gr   = rowBase + row;
            float4 v = make_float4(0.f, 0.f, 0.f, 0.f);
            if (gr < M) v = *(const float4*)&A[(size_t)gr * K + k0 + kq * 4];
            uint2 hi, lo;
            cvt_hilo(v, hi, lo);
            *(uint2*)(smbuf + OFF_AHI + row * ASTR + kq * 8) = hi;
            *(uint2*)(smbuf + OFF_ALO + row * ASTR + kq * 8) = lo;
        }
        // ---- fill B: 32 k-rows x 128 n (1024 float4 slots) ----
        #pragma unroll
        for (int i = 0; i < 4; i++) {
            const int slot = t + i * 256;
            const int row  = slot >> 5;
            const int c4   = slot & 31;
            float4 v = *(const float4*)&Wm[(size_t)(k0 + row) * HDIM + colW + c4 * 4];
            uint2 hi, lo;
            cvt_hilo(v, hi, lo);
            *(uint2*)(smbuf + OFF_BHI + row * BSTR + c4 * 8) = hi;
            *(uint2*)(smbuf + OFF_BLO + row * BSTR + c4 * 8) = lo;
        }
        __syncthreads();

        #pragma unroll
        for (int s = 0; s < 2; s++) {           // two k16 steps
            uint32_t ahi[2][4], alo[2][4];
            #pragma unroll
            for (int mt = 0; mt < 2; mt++) {
                const int row = wm * 32 + mt * 16 + (lane & 15);
                const uint32_t aoff = row * ASTR + (lane >> 4) * 16 + s * 32;
                ldsm4(smb + OFF_AHI + aoff, ahi[mt]);
                ldsm4(smb + OFF_ALO + aoff, alo[mt]);
            }
            #pragma unroll
            for (int np = 0; np < 4; np++) {    // pairs of n8 tiles
                const int g    = lane >> 3;
                const int krow = s * 16 + (g & 1) * 8 + (lane & 7);
                const int ncol = wn * 64 + np * 16 + (g >> 1) * 8;
                const uint32_t boff = krow * BSTR + ncol * 2;
                uint32_t bhi[4], blo[4];
                ldsm4t(smb + OFF_BHI + boff, bhi);
                ldsm4t(smb + OFF_BLO + boff, blo);
                #pragma unroll
                for (int mt = 0; mt < 2; mt++) {
                    #pragma unroll
                    for (int tt = 0; tt < 2; tt++) {
                        float* d = acc[mt][np * 2 + tt];
                        mma_bf16(d, ahi[mt], bhi[2 * tt], bhi[2 * tt + 1]);
                        mma_bf16(d, ahi[mt], blo[2 * tt], blo[2 * tt + 1]);
                        mma_bf16(d, alo[mt], bhi[2 * tt], bhi[2 * tt + 1]);
                    }
                }
            }
        }
        __syncthreads();
    }

    // ---- epilogue: acc + bias -> C ----
    #pragma unroll
    for (int mt = 0; mt < 2; mt++) {
        const int r0 = rowBase + wm * 32 + mt * 16 + (lane >> 2);
        #pragma unroll
        for (int nt = 0; nt < 8; nt++) {
            const int cg = colW + wn * 64 + nt * 8 + (lane & 3) * 2;
            const float2 bv = __ldg((const float2*)&bias[cg]);
            if (r0 < M) {
                float2 v = make_float2(acc[mt][nt][0] + bv.x, acc[mt][nt][1] + bv.y);
                *(float2*)&C[(size_t)r0 * HDIM + cg] = v;
            }
            if (r0 + 8 < M) {
                float2 v = make_float2(acc[mt][nt][2] + bv.x, acc[mt][nt][3] + bv.y);
                *(float2*)&C[(size_t)(r0 + 8) * HDIM + cg] = v;
            }
        }
    }
}

// ---------------- CSR build ----------------
__global__ void deg_kernel(const int* __restrict__ ei, int* __restrict__ deg) {
    int e = blockIdx.x * blockDim.x + threadIdx.x;
    if (e < EE) atomicAdd(&deg[ei[EE + e]], 1);
}

__global__ void scan_block_kernel(const int* __restrict__ deg,
                                  int* __restrict__ excl,
                                  int* __restrict__ partial) {
    __shared__ int tsum[256];
    const int base = blockIdx.x * 1024;
    const int idx0 = base + threadIdx.x * 4;
    int v[4], pre[4];
    #pragma unroll
    for (int j = 0; j < 4; j++) v[j] = (idx0 + j < NN) ? deg[idx0 + j] : 0;
    int run = 0;
    #pragma unroll
    for (int j = 0; j < 4; j++) { pre[j] = run; run += v[j]; }
    tsum[threadIdx.x] = run;
    __syncthreads();
    #pragma unroll
    for (int off = 1; off < 256; off <<= 1) {
        int tv = (threadIdx.x >= off) ? tsum[threadIdx.x - off] : 0;
        __syncthreads();
        tsum[threadIdx.x] += tv;
        __syncthreads();
    }
    const int tOff = (threadIdx.x > 0) ? tsum[threadIdx.x - 1] : 0;
    #pragma unroll
    for (int j = 0; j < 4; j++)
        if (idx0 + j < NN) excl[idx0 + j] = tOff + pre[j];
    if (threadIdx.x == 255) partial[blockIdx.x] = tsum[255];
}

__global__ void scan_partial_kernel(int* __restrict__ partial) {
    if (threadIdx.x == 0) {
        int run = 0;
        for (int i = 0; i < NB_SCAN; i++) { int t = partial[i]; partial[i] = run; run += t; }
    }
}

__global__ void add_offset_kernel(int* __restrict__ rowptr, const int* __restrict__ partial) {
    int i = blockIdx.x * blockDim.x + threadIdx.x;
    if (i < NN) rowptr[i] += partial[i >> 10];
    if (i == 0) rowptr[NN] = EE;
}

__global__ void scatter_kernel(const int* __restrict__ ei,
                               const int* __restrict__ rowptr,
                               int* __restrict__ fill,
                               int* __restrict__ col) {
    int e = blockIdx.x * blockDim.x + threadIdx.x;
    if (e >= EE) return;
    const int dst = ei[EE + e];
    const int p = atomicAdd(&fill[dst], 1);
    col[rowptr[dst] + p] = ei[e];
}

// ---------------- node-major fused GATv2 aggregation ----------------
template <bool SILU>
__global__ void node_aggr_kernel(const int* __restrict__ rowptr,
                                 const int* __restrict__ col,
                                 const float* __restrict__ xl,
                                 const float* __restrict__ xr,
                                 const float* __restrict__ att,
                                 const float* __restrict__ bias,
                                 float* __restrict__ hout) {
    const int node = (blockIdx.x * blockDim.x + threadIdx.x) >> 5;
    const int lane = threadIdx.x & 31;
    if (node >= NN) return;

    const float4* __restrict__ xd = (const float4*)(xr + (size_t)node * HDIM);
    const float4 r0 = xd[lane];
    const float4 r1 = xd[lane + 32];
    const float4 a0 = __ldg(&((const float4*)att)[lane]);
    const float4 a1 = __ldg(&((const float4*)att)[lane + 32]);

    float4 acc0 = make_float4(0.f, 0.f, 0.f, 0.f);
    float4 acc1 = make_float4(0.f, 0.f, 0.f, 0.f);
    float denL = 0.f, denH = 0.f;

    const int pBeg = rowptr[node];
    const int pEnd = rowptr[node + 1];

    float4 l0n, l1n;
    if (pBeg < pEnd) {
        const float4* xs = (const float4*)(xl + (size_t)col[pBeg] * HDIM);
        l0n = xs[lane];
        l1n = xs[lane + 32];
    }

    for (int p = pBeg; p < pEnd; p++) {
        const float4 l0 = l0n;
        const float4 l1 = l1n;
        if (p + 1 < pEnd) {
            const float4* xs = (const float4*)(xl + (size_t)col[p + 1] * HDIM);
            l0n = xs[lane];
            l1n = xs[lane + 32];
        }

        float4 s0, s1;
        s0.x = l0.x + r0.x; s0.y = l0.y + r0.y; s0.z = l0.z + r0.z; s0.w = l0.w + r0.w;
        s1.x = l1.x + r1.x; s1.y = l1.y + r1.y; s1.z = l1.z + r1.z; s1.w = l1.w + r1.w;
        s0.x = s0.x > 0.f ? s0.x : 0.2f * s0.x;
        s0.y = s0.y > 0.f ? s0.y : 0.2f * s0.y;
        s0.z = s0.z > 0.f ? s0.z : 0.2f * s0.z;
        s0.w = s0.w > 0.f ? s0.w : 0.2f * s0.w;
        s1.x = s1.x > 0.f ? s1.x : 0.2f * s1.x;
        s1.y = s1.y > 0.f ? s1.y : 0.2f * s1.y;
        s1.z = s1.z > 0.f ? s1.z : 0.2f * s1.z;
        s1.w = s1.w > 0.f ? s1.w : 0.2f * s1.w;

        float p0 = s0.x * a0.x + s0.y * a0.y + s0.z * a0.z + s0.w * a0.w;
        float p1 = s1.x * a1.x + s1.y * a1.y + s1.z * a1.z + s1.w * a1.w;
        #pragma unroll
        for (int o = 8; o > 0; o >>= 1) {
            p0 += __shfl_xor_sync(0xFFFFFFFFu, p0, o);
            p1 += __shfl_xor_sync(0xFFFFFFFFu, p1, o);
        }
        const float eL = __expf(p0);
        const float eH = __expf(p1);

        acc0.x = fmaf(l0.x, eL, acc0.x); acc0.y = fmaf(l0.y, eL, acc0.y);
        acc0.z = fmaf(l0.z, eL, acc0.z); acc0.w = fmaf(l0.w, eL, acc0.w);
        acc1.x = fmaf(l1.x, eH, acc1.x); acc1.y = fmaf(l1.y, eH, acc1.y);
        acc1.z = fmaf(l1.z, eH, acc1.z); acc1.w = fmaf(l1.w, eH, acc1.w);
        denL += eL;
        denH += eH;
    }

    const float invL = 1.0f / (denL + 1e-16f);
    const float invH = 1.0f / (denH + 1e-16f);
    const float4 b0 = __ldg(&((const float4*)bias)[lane]);
    const float4 b1 = __ldg(&((const float4*)bias)[lane + 32]);

    float4 o0, o1;
    o0.x = acc0.x * invL + b0.x; o0.y = acc0.y * invL + b0.y;
    o0.z = acc0.z * invL + b0.z; o0.w = acc0.w * invL + b0.w;
    o1.x = acc1.x * invH + b1.x; o1.y = acc1.y * invH + b1.y;
    o1.z = acc1.z * invH + b1.z; o1.w = acc1.w * invH + b1.w;
    if (SILU) {
        o0.x = o0.x / (1.0f + __expf(-o0.x));
        o0.y = o0.y / (1.0f + __expf(-o0.y));
        o0.z = o0.z / (1.0f + __expf(-o0.z));
        o0.w = o0.w / (1.0f + __expf(-o0.w));
        o1.x = o1.x / (1.0f + __expf(-o1.x));
        o1.y = o1.y / (1.0f + __expf(-o1.y));
        o1.z = o1.z / (1.0f + __expf(-o1.z));
        o1.w = o1.w / (1.0f + __expf(-o1.w));
    }
    float4* ho = (float4*)(hout + (size_t)node * HDIM);
    ho[lane]      = o0;
    ho[lane + 32] = o1;
}

// ---------------- global mean pool (batch is SORTED) ----------------
// Block b owns nodes [b*256, (b+1)*256); thread t owns column t.
// Sequential coalesced reads; atomics only on group boundaries.
__global__ void pool_sorted_kernel(const float* __restrict__ h,
                                   const int* __restrict__ batch,
                                   float* __restrict__ out,
                                   float* __restrict__ cnt) {
    __shared__ int sg[256];
    const int t = threadIdx.x;
    const int n0 = blockIdx.x * 256;
    const int n1 = min(n0 + 256, NN);
    // preload this block's batch ids
    if (n0 + t < NN) sg[t] = batch[n0 + t];
    __syncthreads();

    float acc = 0.0f;
    int curG = sg[0];
    int cntLocal = 0;
    for (int n = n0; n < n1; n++) {
        const int g = sg[n - n0];
        if (g != curG) {
            atomicAdd(&out[curG * HDIM + t], acc);
            if (t == 0) atomicAdd(&cnt[curG], (float)cntLocal);
            acc = 0.0f;
            cntLocal = 0;
            curG = g;
        }
        acc += h[(size_t)n * HDIM + t];
        cntLocal++;
    }
    atomicAdd(&out[curG * HDIM + t], acc);
    if (t == 0) atomicAdd(&cnt[curG], (float)cntLocal);
}

__global__ void pool_div_kernel(float* __restrict__ out, const float* __restrict__ cnt) {
    int i = blockIdx.x * blockDim.x + threadIdx.x;
    if (i < GG * HDIM) out[i] = out[i] / fmaxf(cnt[i >> 8], 1.0f);
}

// ---------------- launch ----------------
extern "C" void kernel_launch(void* const* d_in, const int* in_sizes, int n_in,
                              void* d_out, int out_size) {
    const float* x     = (const float*)d_in[0];
    const int*   ei    = (const int*)  d_in[1];
    const int*   batch = (const int*)  d_in[2];
    const float* Wl1   = (const float*)d_in[3];
    const float* bl1   = (const float*)d_in[4];
    const float* Wr1   = (const float*)d_in[5];
    const float* br1   = (const float*)d_in[6];
    const float* att1  = (const float*)d_in[7];
    const float* bias1 = (const float*)d_in[8];
    const float* Wl2   = (const float*)d_in[9];
    const float* bl2   = (const float*)d_in[10];
    const float* Wr2   = (const float*)d_in[11];
    const float* br2   = (const float*)d_in[12];
    const float* att2  = (const float*)d_in[13];
    const float* bias2 = (const float*)d_in[14];
    float* out = (float*)d_out;

    float *xl, *xr, *h1, *h2, *cnt;
    int *deg, *fill, *rowptr, *colA, *partial;
    cudaGetSymbolAddress((void**)&xl,      g_xl);
    cudaGetSymbolAddress((void**)&xr,      g_xr);
    cudaGetSymbolAddress((void**)&h1,      g_h1);
    cudaGetSymbolAddress((void**)&h2,      g_h2);
    cudaGetSymbolAddress((void**)&cnt,     g_cnt);
    cudaGetSymbolAddress((void**)&deg,     g_deg);
    cudaGetSymbolAddress((void**)&fill,    g_fill);
    cudaGetSymbolAddress((void**)&rowptr,  g_rowptr);
    cudaGetSymbolAddress((void**)&colA,    g_col);
    cudaGetSymbolAddress((void**)&partial, g_partial);

    const dim3 ggrid(4, (NN + 127) / 128);
    const int ebE = (EE + 255) / 256;
    const int nwb = (NN * 32 + 255) / 256;

    // ---- CSR build (used by both layers) ----
    cudaMemsetAsync(deg, 0, NN * sizeof(int));
    cudaMemsetAsync(fill, 0, NN * sizeof(int));
    deg_kernel<<<ebE, 256>>>(ei, deg);
    scan_block_kernel<<<NB_SCAN, 256>>>(deg, rowptr, partial);
    scan_partial_kernel<<<1, 32>>>(partial);
    add_offset_kernel<<<(NN + 255) / 256, 256>>>(rowptr, partial);
    scatter_kernel<<<ebE, 256>>>(ei, rowptr, fill, colA);

    // ---- layer 1 ----
    gemm_mma_kernel<<<ggrid, 256>>>(x, Wl1, Wr1, bl1, br1, xl, xr, NN, 128);
    node_aggr_kernel<true><<<nwb, 256>>>(rowptr, colA, xl, xr, att1, bias1, h1);

    // ---- layer 2 ----
    gemm_mma_kernel<<<ggrid, 256>>>(h1, Wl2, Wr2, bl2, br2, xl, xr, NN, 256);
    node_aggr_kernel<false><<<nwb, 256>>>(rowptr, colA, xl, xr, att2, bias2, h2);

    // ---- global mean pool (sorted batch) ----
    cudaMemsetAsync(out, 0, (size_t)GG * HDIM * sizeof(float));
    cudaMemsetAsync(cnt, 0, (size_t)GG * sizeof(float));
    pool_sorted_kernel<<<(NN + 255) / 256, 256>>>(h2, batch, out, cnt);
    pool_div_kernel<<<(GG * HDIM + 255) / 256, 256>>>(out, cnt);
}

// round 9
// speedup vs baseline: 1.0799x; 1.0394x over previous
#include <cuda_runtime.h>
#include <cuda_bf16.h>
#include <cuda_fp16.h>
#include <math.h>
#include <stdint.h>

// Problem constants (fixed shapes per reference)
#define NN   50000
#define EE   800000
#define GG   64
#define HH   4
#define HDIM 256   // 4 heads * 64
#define NB_SCAN ((NN + 1023) / 1024)

// ---------------- scratch (static device memory; no allocs) ----------------
__device__ __align__(16) __half g_xl[NN * HDIM];   // fp16 transformed features
__device__ __align__(16) __half g_xr[NN * HDIM];
__device__ __align__(16) float g_h1[NN * HDIM];
__device__ __align__(16) float g_h2[NN * HDIM];
__device__ __align__(16) float g_cnt[GG];
__device__ int g_deg[NN];
__device__ int g_fill[NN];
__device__ int g_rowptr[NN + 1];
__device__ int g_col[EE];
__device__ int g_partial[NB_SCAN];

// ================= bf16 3-pass mma.sync GEMM =================
// Block tile 128x128, BK=32, 8 warps (warp tile m32 x n64).
// smem: A_hi/A_lo 128 rows x 32 bf16 (stride 80B), B_hi/B_lo 32 x 128 (stride 272B).
#define ASTR 80
#define BSTR 272
#define OFF_AHI 0
#define OFF_ALO (128 * ASTR)                   // 10240
#define OFF_BHI (2 * 128 * ASTR)               // 20480
#define OFF_BLO (2 * 128 * ASTR + 32 * BSTR)   // 29184
#define SM_GEMM (2 * 128 * ASTR + 2 * 32 * BSTR)   // 37888 bytes

static __device__ __forceinline__ uint32_t smem_u32(const void* p) {
    uint32_t a;
    asm("{ .reg .u64 t; cvta.to.shared.u64 t, %1; cvt.u32.u64 %0, t; }"
        : "=r"(a) : "l"(p));
    return a;
}
static __device__ __forceinline__ unsigned short bf_us(float x) {
    __nv_bfloat16 h = __float2bfloat16_rn(x);
    return *(unsigned short*)&h;
}
static __device__ __forceinline__ float bf_f(unsigned short u) {
    __nv_bfloat16 h = *(__nv_bfloat16*)&u;
    return __bfloat162float(h);
}
static __device__ __forceinline__ void cvt_hilo(float4 v, uint2& hi, uint2& lo) {
    unsigned short h0 = bf_us(v.x), h1 = bf_us(v.y), h2 = bf_us(v.z), h3 = bf_us(v.w);
    unsigned short l0 = bf_us(v.x - bf_f(h0));
    unsigned short l1 = bf_us(v.y - bf_f(h1));
    unsigned short l2 = bf_us(v.z - bf_f(h2));
    unsigned short l3 = bf_us(v.w - bf_f(h3));
    hi.x = (uint32_t)h0 | ((uint32_t)h1 << 16);
    hi.y = (uint32_t)h2 | ((uint32_t)h3 << 16);
    lo.x = (uint32_t)l0 | ((uint32_t)l1 << 16);
    lo.y = (uint32_t)l2 | ((uint32_t)l3 << 16);
}
static __device__ __forceinline__ void ldsm4(uint32_t addr, uint32_t* r) {
    asm volatile("ldmatrix.sync.aligned.m8n8.x4.shared.b16 {%0,%1,%2,%3}, [%4];"
                 : "=r"(r[0]), "=r"(r[1]), "=r"(r[2]), "=r"(r[3]) : "r"(addr));
}
static __device__ __forceinline__ void ldsm4t(uint32_t addr, uint32_t* r) {
    asm volatile("ldmatrix.sync.aligned.m8n8.x4.trans.shared.b16 {%0,%1,%2,%3}, [%4];"
                 : "=r"(r[0]), "=r"(r[1]), "=r"(r[2]), "=r"(r[3]) : "r"(addr));
}
static __device__ __forceinline__ void mma_bf16(float* d, const uint32_t* a,
                                                uint32_t b0, uint32_t b1) {
    asm volatile(
        "mma.sync.aligned.m16n8k16.row.col.f32.bf16.bf16.f32 "
        "{%0,%1,%2,%3}, {%4,%5,%6,%7}, {%8,%9}, {%0,%1,%2,%3};"
        : "+f"(d[0]), "+f"(d[1]), "+f"(d[2]), "+f"(d[3])
        : "r"(a[0]), "r"(a[1]), "r"(a[2]), "r"(a[3]), "r"(b0), "r"(b1));
}
// unpack 4 halves (as uint2) -> float4
static __device__ __forceinline__ float4 h4f(uint2 u) {
    __half2 a = *(__half2*)&u.x;
    __half2 b = *(__half2*)&u.y;
    float2 fa = __half22float2(a);
    float2 fb = __half22float2(b);
    return make_float4(fa.x, fa.y, fb.x, fb.y);
}

// C0 = A@W0 + b0 (blockIdx.x<2) / C1 = A@W1 + b1 ; colBase=(x&1)*128
// C output is fp16.
__global__ void __launch_bounds__(256, 2)
gemm_mma_kernel(const float* __restrict__ A,
                const float* __restrict__ W0, const float* __restrict__ W1,
                const float* __restrict__ b0, const float* __restrict__ b1,
                __half* __restrict__ C0, __half* __restrict__ C1,
                int M, int K) {
    __shared__ __align__(16) unsigned char smbuf[SM_GEMM];
    const uint32_t smb = smem_u32(smbuf);

    const int t    = threadIdx.x;
    const int lane = t & 31;
    const int wid  = t >> 5;
    const int wm   = wid & 3;          // 4 warps over M (32 rows each)
    const int wn   = wid >> 2;         // 2 warps over N (64 cols each)
    const int rowBase = blockIdx.y * 128;
    const int colW    = (blockIdx.x & 1) * 128;

    const float* __restrict__ Wm   = (blockIdx.x < 2) ? W0 : W1;
    const float* __restrict__ bias = (blockIdx.x < 2) ? b0 : b1;
    __half* __restrict__ C         = (blockIdx.x < 2) ? C0 : C1;

    float acc[2][8][4];
    #pragma unroll
    for (int i = 0; i < 2; i++)
        #pragma unroll
        for (int j = 0; j < 8; j++)
            #pragma unroll
            for (int q = 0; q < 4; q++) acc[i][j][q] = 0.0f;

    for (int k0 = 0; k0 < K; k0 += 32) {
        // ---- fill A: 128 rows x 32 k (1024 float4 slots) ----
        #pragma unroll
        for (int i = 0; i < 4; i++) {
            const int slot = t + i * 256;
            const int row  = slot >> 3;
            const int kq   = slot & 7;
            const int gr   = rowBase + row;
            float4 v = make_float4(0.f, 0.f, 0.f, 0.f);
            if (gr < M) v = *(const float4*)&A[(size_t)gr * K + k0 + kq * 4];
            uint2 hi, lo;
            cvt_hilo(v, hi, lo);
            *(uint2*)(smbuf + OFF_AHI + row * ASTR + kq * 8) = hi;
            *(uint2*)(smbuf + OFF_ALO + row * ASTR + kq * 8) = lo;
        }
        // ---- fill B: 32 k-rows x 128 n (1024 float4 slots) ----
        #pragma unroll
        for (int i = 0; i < 4; i++) {
            const int slot = t + i * 256;
            const int row  = slot >> 5;
            const int c4   = slot & 31;
            float4 v = *(const float4*)&Wm[(size_t)(k0 + row) * HDIM + colW + c4 * 4];
            uint2 hi, lo;
            cvt_hilo(v, hi, lo);
            *(uint2*)(smbuf + OFF_BHI + row * BSTR + c4 * 8) = hi;
            *(uint2*)(smbuf + OFF_BLO + row * BSTR + c4 * 8) = lo;
        }
        __syncthreads();

        #pragma unroll
        for (int s = 0; s < 2; s++) {           // two k16 steps
            uint32_t ahi[2][4], alo[2][4];
            #pragma unroll
            for (int mt = 0; mt < 2; mt++) {
                const int row = wm * 32 + mt * 16 + (lane & 15);
                const uint32_t aoff = row * ASTR + (lane >> 4) * 16 + s * 32;
                ldsm4(smb + OFF_AHI + aoff, ahi[mt]);
                ldsm4(smb + OFF_ALO + aoff, alo[mt]);
            }
            #pragma unroll
            for (int np = 0; np < 4; np++) {    // pairs of n8 tiles
                const int g    = lane >> 3;
                const int krow = s * 16 + (g & 1) * 8 + (lane & 7);
                const int ncol = wn * 64 + np * 16 + (g >> 1) * 8;
                const uint32_t boff = krow * BSTR + ncol * 2;
                uint32_t bhi[4], blo[4];
                ldsm4t(smb + OFF_BHI + boff, bhi);
                ldsm4t(smb + OFF_BLO + boff, blo);
                #pragma unroll
                for (int mt = 0; mt < 2; mt++) {
                    #pragma unroll
                    for (int tt = 0; tt < 2; tt++) {
                        float* d = acc[mt][np * 2 + tt];
                        mma_bf16(d, ahi[mt], bhi[2 * tt], bhi[2 * tt + 1]);
                        mma_bf16(d, ahi[mt], blo[2 * tt], blo[2 * tt + 1]);
                        mma_bf16(d, alo[mt], bhi[2 * tt], bhi[2 * tt + 1]);
                    }
                }
            }
        }
        __syncthreads();
    }

    // ---- epilogue: acc + bias -> fp16 C ----
    #pragma unroll
    for (int mt = 0; mt < 2; mt++) {
        const int r0 = rowBase + wm * 32 + mt * 16 + (lane >> 2);
        #pragma unroll
        for (int nt = 0; nt < 8; nt++) {
            const int cg = colW + wn * 64 + nt * 8 + (lane & 3) * 2;
            const float2 bv = __ldg((const float2*)&bias[cg]);
            if (r0 < M) {
                __half2 hv = __floats2half2_rn(acc[mt][nt][0] + bv.x,
                                               acc[mt][nt][1] + bv.y);
                *(__half2*)&C[(size_t)r0 * HDIM + cg] = hv;
            }
            if (r0 + 8 < M) {
                __half2 hv = __floats2half2_rn(acc[mt][nt][2] + bv.x,
                                               acc[mt][nt][3] + bv.y);
                *(__half2*)&C[(size_t)(r0 + 8) * HDIM + cg] = hv;
            }
        }
    }
}

// ---------------- CSR build ----------------
__global__ void deg_kernel(const int* __restrict__ ei, int* __restrict__ deg) {
    int e = blockIdx.x * blockDim.x + threadIdx.x;
    if (e < EE) atomicAdd(&deg[ei[EE + e]], 1);
}

__global__ void scan_block_kernel(const int* __restrict__ deg,
                                  int* __restrict__ excl,
                                  int* __restrict__ partial) {
    __shared__ int tsum[256];
    const int base = blockIdx.x * 1024;
    const int idx0 = base + threadIdx.x * 4;
    int v[4], pre[4];
    #pragma unroll
    for (int j = 0; j < 4; j++) v[j] = (idx0 + j < NN) ? deg[idx0 + j] : 0;
    int run = 0;
    #pragma unroll
    for (int j = 0; j < 4; j++) { pre[j] = run; run += v[j]; }
    tsum[threadIdx.x] = run;
    __syncthreads();
    #pragma unroll
    for (int off = 1; off < 256; off <<= 1) {
        int tv = (threadIdx.x >= off) ? tsum[threadIdx.x - off] : 0;
        __syncthreads();
        tsum[threadIdx.x] += tv;
        __syncthreads();
    }
    const int tOff = (threadIdx.x > 0) ? tsum[threadIdx.x - 1] : 0;
    #pragma unroll
    for (int j = 0; j < 4; j++)
        if (idx0 + j < NN) excl[idx0 + j] = tOff + pre[j];
    if (threadIdx.x == 255) partial[blockIdx.x] = tsum[255];
}

__global__ void scan_partial_kernel(int* __restrict__ partial) {
    if (threadIdx.x == 0) {
        int run = 0;
        for (int i = 0; i < NB_SCAN; i++) { int t = partial[i]; partial[i] = run; run += t; }
    }
}

__global__ void add_offset_kernel(int* __restrict__ rowptr, const int* __restrict__ partial) {
    int i = blockIdx.x * blockDim.x + threadIdx.x;
    if (i < NN) rowptr[i] += partial[i >> 10];
    if (i == 0) rowptr[NN] = EE;
}

__global__ void scatter_kernel(const int* __restrict__ ei,
                               const int* __restrict__ rowptr,
                               int* __restrict__ fill,
                               int* __restrict__ col) {
    int e = blockIdx.x * blockDim.x + threadIdx.x;
    if (e >= EE) return;
    const int dst = ei[EE + e];
    const int p = atomicAdd(&fill[dst], 1);
    col[rowptr[dst] + p] = ei[e];
}

// ---------------- node-major fused GATv2 aggregation (fp16 inputs) ----------------
template <bool SILU>
__global__ void node_aggr_kernel(const int* __restrict__ rowptr,
                                 const int* __restrict__ col,
                                 const __half* __restrict__ xl,
                                 const __half* __restrict__ xr,
                                 const float* __restrict__ att,
                                 const float* __restrict__ bias,
                                 float* __restrict__ hout) {
    const int node = (blockIdx.x * blockDim.x + threadIdx.x) >> 5;
    const int lane = threadIdx.x & 31;
    if (node >= NN) return;

    // uint2 = 4 halves; row = 64 uint2 slots. Lane handles slots lane, lane+32
    // -> identical element mapping to the old float4 layout.
    const uint2* __restrict__ xd = (const uint2*)(xr + (size_t)node * HDIM);
    const float4 r0 = h4f(xd[lane]);
    const float4 r1 = h4f(xd[lane + 32]);
    const float4 a0 = __ldg(&((const float4*)att)[lane]);
    const float4 a1 = __ldg(&((const float4*)att)[lane + 32]);

    float4 acc0 = make_float4(0.f, 0.f, 0.f, 0.f);
    float4 acc1 = make_float4(0.f, 0.f, 0.f, 0.f);
    float denL = 0.f, denH = 0.f;

    const int pBeg = rowptr[node];
    const int pEnd = rowptr[node + 1];

    uint2 p0n, p1n;
    if (pBeg < pEnd) {
        const uint2* xs = (const uint2*)(xl + (size_t)col[pBeg] * HDIM);
        p0n = xs[lane];
        p1n = xs[lane + 32];
    }

    for (int p = pBeg; p < pEnd; p++) {
        const float4 l0 = h4f(p0n);
        const float4 l1 = h4f(p1n);
        if (p + 1 < pEnd) {                     // prefetch next src row
            const uint2* xs = (const uint2*)(xl + (size_t)col[p + 1] * HDIM);
            p0n = xs[lane];
            p1n = xs[lane + 32];
        }

        float4 s0, s1;
        s0.x = l0.x + r0.x; s0.y = l0.y + r0.y; s0.z = l0.z + r0.z; s0.w = l0.w + r0.w;
        s1.x = l1.x + r1.x; s1.y = l1.y + r1.y; s1.z = l1.z + r1.z; s1.w = l1.w + r1.w;
        s0.x = s0.x > 0.f ? s0.x : 0.2f * s0.x;
        s0.y = s0.y > 0.f ? s0.y : 0.2f * s0.y;
        s0.z = s0.z > 0.f ? s0.z : 0.2f * s0.z;
        s0.w = s0.w > 0.f ? s0.w : 0.2f * s0.w;
        s1.x = s1.x > 0.f ? s1.x : 0.2f * s1.x;
        s1.y = s1.y > 0.f ? s1.y : 0.2f * s1.y;
        s1.z = s1.z > 0.f ? s1.z : 0.2f * s1.z;
        s1.w = s1.w > 0.f ? s1.w : 0.2f * s1.w;

        float q0 = s0.x * a0.x + s0.y * a0.y + s0.z * a0.z + s0.w * a0.w;
        float q1 = s1.x * a1.x + s1.y * a1.y + s1.z * a1.z + s1.w * a1.w;
        #pragma unroll
        for (int o = 8; o > 0; o >>= 1) {       // reduce within 16-lane group
            q0 += __shfl_xor_sync(0xFFFFFFFFu, q0, o);
            q1 += __shfl_xor_sync(0xFFFFFFFFu, q1, o);
        }
        // group g = lane>>4: q0 = score(head g), q1 = score(head 2+g)
        const float eL = __expf(q0);
        const float eH = __expf(q1);

        acc0.x = fmaf(l0.x, eL, acc0.x); acc0.y = fmaf(l0.y, eL, acc0.y);
        acc0.z = fmaf(l0.z, eL, acc0.z); acc0.w = fmaf(l0.w, eL, acc0.w);
        acc1.x = fmaf(l1.x, eH, acc1.x); acc1.y = fmaf(l1.y, eH, acc1.y);
        acc1.z = fmaf(l1.z, eH, acc1.z); acc1.w = fmaf(l1.w, eH, acc1.w);
        denL += eL;
        denH += eH;
    }

    const float invL = 1.0f / (denL + 1e-16f);
    const float invH = 1.0f / (denH + 1e-16f);
    const float4 b0 = __ldg(&((const float4*)bias)[lane]);
    const float4 b1 = __ldg(&((const float4*)bias)[lane + 32]);

    float4 o0, o1;
    o0.x = acc0.x * invL + b0.x; o0.y = acc0.y * invL + b0.y;
    o0.z = acc0.z * invL + b0.z; o0.w = acc0.w * invL + b0.w;
    o1.x = acc1.x * invH + b1.x; o1.y = acc1.y * invH + b1.y;
    o1.z = acc1.z * invH + b1.z; o1.w = acc1.w * invH + b1.w;
    if (SILU) {
        o0.x = o0.x / (1.0f + __expf(-o0.x));
        o0.y = o0.y / (1.0f + __expf(-o0.y));
        o0.z = o0.z / (1.0f + __expf(-o0.z));
        o0.w = o0.w / (1.0f + __expf(-o0.w));
        o1.x = o1.x / (1.0f + __expf(-o1.x));
        o1.y = o1.y / (1.0f + __expf(-o1.y));
        o1.z = o1.z / (1.0f + __expf(-o1.z));
        o1.w = o1.w / (1.0f + __expf(-o1.w));
    }
    float4* ho = (float4*)(hout + (size_t)node * HDIM);
    ho[lane]      = o0;
    ho[lane + 32] = o1;
}

// ---------------- global mean pool (batch is SORTED) ----------------
__global__ void pool_sorted_kernel(const float* __restrict__ h,
                                   const int* __restrict__ batch,
                                   float* __restrict__ out,
                                   float* __restrict__ cnt) {
    __shared__ int sg[256];
    const int t = threadIdx.x;
    const int n0 = blockIdx.x * 256;
    const int n1 = min(n0 + 256, NN);
    if (n0 + t < NN) sg[t] = batch[n0 + t];
    __syncthreads();

    float acc = 0.0f;
    int curG = sg[0];
    int cntLocal = 0;
    for (int n = n0; n < n1; n++) {
        const int g = sg[n - n0];
        if (g != curG) {
            atomicAdd(&out[curG * HDIM + t], acc);
            if (t == 0) atomicAdd(&cnt[curG], (float)cntLocal);
            acc = 0.0f;
            cntLocal = 0;
            curG = g;
        }
        acc += h[(size_t)n * HDIM + t];
        cntLocal++;
    }
    atomicAdd(&out[curG * HDIM + t], acc);
    if (t == 0) atomicAdd(&cnt[curG], (float)cntLocal);
}

__global__ void pool_div_kernel(float* __restrict__ out, const float* __restrict__ cnt) {
    int i = blockIdx.x * blockDim.x + threadIdx.x;
    if (i < GG * HDIM) out[i] = out[i] / fmaxf(cnt[i >> 8], 1.0f);
}

// ---------------- launch ----------------
extern "C" void kernel_launch(void* const* d_in, const int* in_sizes, int n_in,
                              void* d_out, int out_size) {
    const float* x     = (const float*)d_in[0];
    const int*   ei    = (const int*)  d_in[1];
    const int*   batch = (const int*)  d_in[2];
    const float* Wl1   = (const float*)d_in[3];
    const float* bl1   = (const float*)d_in[4];
    const float* Wr1   = (const float*)d_in[5];
    const float* br1   = (const float*)d_in[6];
    const float* att1  = (const float*)d_in[7];
    const float* bias1 = (const float*)d_in[8];
    const float* Wl2   = (const float*)d_in[9];
    const float* bl2   = (const float*)d_in[10];
    const float* Wr2   = (const float*)d_in[11];
    const float* br2   = (const float*)d_in[12];
    const float* att2  = (const float*)d_in[13];
    const float* bias2 = (const float*)d_in[14];
    float* out = (float*)d_out;

    __half *xl, *xr;
    float *h1, *h2, *cnt;
    int *deg, *fill, *rowptr, *colA, *partial;
    cudaGetSymbolAddress((void**)&xl,      g_xl);
    cudaGetSymbolAddress((void**)&xr,      g_xr);
    cudaGetSymbolAddress((void**)&h1,      g_h1);
    cudaGetSymbolAddress((void**)&h2,      g_h2);
    cudaGetSymbolAddress((void**)&cnt,     g_cnt);
    cudaGetSymbolAddress((void**)&deg,     g_deg);
    cudaGetSymbolAddress((void**)&fill,    g_fill);
    cudaGetSymbolAddress((void**)&rowptr,  g_rowptr);
    cudaGetSymbolAddress((void**)&colA,    g_col);
    cudaGetSymbolAddress((void**)&partial, g_partial);

    const dim3 ggrid(4, (NN + 127) / 128);
    const int ebE = (EE + 255) / 256;
    const int nwb = (NN * 32 + 255) / 256;

    // ---- CSR build (used by both layers) ----
    cudaMemsetAsync(deg, 0, NN * sizeof(int));
    cudaMemsetAsync(fill, 0, NN * sizeof(int));
    deg_kernel<<<ebE, 256>>>(ei, deg);
    scan_block_kernel<<<NB_SCAN, 256>>>(deg, rowptr, partial);
    scan_partial_kernel<<<1, 32>>>(partial);
    add_offset_kernel<<<(NN + 255) / 256, 256>>>(rowptr, partial);
    scatter_kernel<<<ebE, 256>>>(ei, rowptr, fill, colA);

    // ---- layer 1 ----
    gemm_mma_kernel<<<ggrid, 256>>>(x, Wl1, Wr1, bl1, br1, xl, xr, NN, 128);
    node_aggr_kernel<true><<<nwb, 256>>>(rowptr, colA, xl, xr, att1, bias1, h1);

    // ---- layer 2 ----
    gemm_mma_kernel<<<ggrid, 256>>>(h1, Wl2, Wr2, bl2, br2, xl, xr, NN, 256);
    node_aggr_kernel<false><<<nwb, 256>>>(rowptr, colA, xl, xr, att2, bias2, h2);

    // ---- global mean pool (sorted batch) ----
    cudaMemsetAsync(out, 0, (size_t)GG * HDIM * sizeof(float));
    cudaMemsetAsync(cnt, 0, (size_t)GG * sizeof(float));
    pool_sorted_kernel<<<(NN + 255) / 256, 256>>>(h2, batch, out, cnt);
    pool_div_kernel<<<(GG * HDIM + 255) / 256, 256>>>(out, cnt);
}

// round 10
// speedup vs baseline: 1.2903x; 1.1949x over previous
#include <cuda_runtime.h>
#include <cuda_fp16.h>
#include <math.h>
#include <stdint.h>

// Problem constants (fixed shapes per reference)
#define NN   50000
#define EE   800000
#define GG   64
#define HH   4
#define HDIM 256   // 4 heads * 64
#define NB_SCAN ((NN + 1023) / 1024)

// ---------------- scratch (static device memory; no allocs) ----------------
__device__ __align__(16) __half g_xl[NN * HDIM];   // fp16 transformed features
__device__ __align__(16) __half g_xr[NN * HDIM];
__device__ __align__(16) __half g_h1[NN * HDIM];   // fp16 layer-1 output
__device__ __align__(16) float g_h2[NN * HDIM];
__device__ __align__(16) float g_cnt[GG];
__device__ int g_deg[NN];
__device__ int g_fill[NN];
__device__ int g_rowptr[NN + 1];
__device__ int g_col[EE];
__device__ int g_partial[NB_SCAN];

// ================= single-pass fp16 mma.sync GEMM =================
// Block tile 128x128, BK=32, 8 warps (warp tile m32 x n64).
// smem: A 128 rows x 32 fp16 (stride 80B), B 32 k-rows x 128 fp16 (stride 272B).
#define ASTR 80
#define BSTR 272
#define OFF_A 0
#define OFF_B (128 * ASTR)                 // 10240
#define SM_GEMM (128 * ASTR + 32 * BSTR)   // 18944 bytes

static __device__ __forceinline__ uint32_t smem_u32(const void* p) {
    uint32_t a;
    asm("{ .reg .u64 t; cvta.to.shared.u64 t, %1; cvt.u32.u64 %0, t; }"
        : "=r"(a) : "l"(p));
    return a;
}
static __device__ __forceinline__ uint2 f4_to_h4(float4 v) {
    __half2 h01 = __floats2half2_rn(v.x, v.y);
    __half2 h23 = __floats2half2_rn(v.z, v.w);
    uint2 u;
    u.x = *(uint32_t*)&h01;
    u.y = *(uint32_t*)&h23;
    return u;
}
static __device__ __forceinline__ void ldsm4(uint32_t addr, uint32_t* r) {
    asm volatile("ldmatrix.sync.aligned.m8n8.x4.shared.b16 {%0,%1,%2,%3}, [%4];"
                 : "=r"(r[0]), "=r"(r[1]), "=r"(r[2]), "=r"(r[3]) : "r"(addr));
}
static __device__ __forceinline__ void ldsm4t(uint32_t addr, uint32_t* r) {
    asm volatile("ldmatrix.sync.aligned.m8n8.x4.trans.shared.b16 {%0,%1,%2,%3}, [%4];"
                 : "=r"(r[0]), "=r"(r[1]), "=r"(r[2]), "=r"(r[3]) : "r"(addr));
}
static __device__ __forceinline__ void mma_f16(float* d, const uint32_t* a,
                                               uint32_t b0, uint32_t b1) {
    asm volatile(
        "mma.sync.aligned.m16n8k16.row.col.f32.f16.f16.f32 "
        "{%0,%1,%2,%3}, {%4,%5,%6,%7}, {%8,%9}, {%0,%1,%2,%3};"
        : "+f"(d[0]), "+f"(d[1]), "+f"(d[2]), "+f"(d[3])
        : "r"(a[0]), "r"(a[1]), "r"(a[2]), "r"(a[3]), "r"(b0), "r"(b1));
}
// unpack 4 halves (as uint2) -> float4
static __device__ __forceinline__ float4 h4f(uint2 u) {
    __half2 a = *(__half2*)&u.x;
    __half2 b = *(__half2*)&u.y;
    float2 fa = __half22float2(a);
    float2 fb = __half22float2(b);
    return make_float4(fa.x, fa.y, fb.x, fb.y);
}

// C0 = A@W0 + b0 (blockIdx.x<2) / C1 = A@W1 + b1 ; colBase=(x&1)*128
// AHALF: A is fp16 (layer 2); else fp32 (layer 1). C output is fp16.
template <bool AHALF>
__global__ void __launch_bounds__(256, 2)
gemm_f16_kernel(const float* __restrict__ Af, const __half* __restrict__ Ah,
                const float* __restrict__ W0, const float* __restrict__ W1,
                const float* __restrict__ b0, const float* __restrict__ b1,
                __half* __restrict__ C0, __half* __restrict__ C1,
                int M, int K) {
    __shared__ __align__(16) unsigned char smbuf[SM_GEMM];
    const uint32_t smb = smem_u32(smbuf);

    const int t    = threadIdx.x;
    const int lane = t & 31;
    const int wid  = t >> 5;
    const int wm   = wid & 3;          // 4 warps over M (32 rows each)
    const int wn   = wid >> 2;         // 2 warps over N (64 cols each)
    const int rowBase = blockIdx.y * 128;
    const int colW    = (blockIdx.x & 1) * 128;

    const float* __restrict__ Wm   = (blockIdx.x < 2) ? W0 : W1;
    const float* __restrict__ bias = (blockIdx.x < 2) ? b0 : b1;
    __half* __restrict__ C         = (blockIdx.x < 2) ? C0 : C1;

    float acc[2][8][4];
    #pragma unroll
    for (int i = 0; i < 2; i++)
        #pragma unroll
        for (int j = 0; j < 8; j++)
            #pragma unroll
            for (int q = 0; q < 4; q++) acc[i][j][q] = 0.0f;

    for (int k0 = 0; k0 < K; k0 += 32) {
        // ---- fill A: 128 rows x 32 k = 1024 4-half slots ----
        #pragma unroll
        for (int i = 0; i < 4; i++) {
            const int slot = t + i * 256;
            const int row  = slot >> 3;
            const int kq   = slot & 7;
            const int gr   = rowBase + row;
            uint2 u = make_uint2(0u, 0u);
            if (gr < M) {
                if (AHALF) {
                    u = *(const uint2*)&Ah[(size_t)gr * K + k0 + kq * 4];
                } else {
                    float4 v = *(const float4*)&Af[(size_t)gr * K + k0 + kq * 4];
                    u = f4_to_h4(v);
                }
            }
            *(uint2*)(smbuf + OFF_A + row * ASTR + kq * 8) = u;
        }
        // ---- fill B: 32 k-rows x 128 n = 1024 4-half slots ----
        #pragma unroll
        for (int i = 0; i < 4; i++) {
            const int slot = t + i * 256;
            const int row  = slot >> 5;
            const int c4   = slot & 31;
            float4 v = *(const float4*)&Wm[(size_t)(k0 + row) * HDIM + colW + c4 * 4];
            *(uint2*)(smbuf + OFF_B + row * BSTR + c4 * 8) = f4_to_h4(v);
        }
        __syncthreads();

        #pragma unroll
        for (int s = 0; s < 2; s++) {           // two k16 steps
            uint32_t av[2][4];
            #pragma unroll
            for (int mt = 0; mt < 2; mt++) {
                const int row = wm * 32 + mt * 16 + (lane & 15);
                const uint32_t aoff = row * ASTR + (lane >> 4) * 16 + s * 32;
                ldsm4(smb + OFF_A + aoff, av[mt]);
            }
            #pragma unroll
            for (int np = 0; np < 4; np++) {    // pairs of n8 tiles
                const int g    = lane >> 3;
                const int krow = s * 16 + (g & 1) * 8 + (lane & 7);
                const int ncol = wn * 64 + np * 16 + (g >> 1) * 8;
                const uint32_t boff = krow * BSTR + ncol * 2;
                uint32_t bv[4];
                ldsm4t(smb + OFF_B + boff, bv);
                #pragma unroll
                for (int mt = 0; mt < 2; mt++) {
                    #pragma unroll
                    for (int tt = 0; tt < 2; tt++) {
                        mma_f16(acc[mt][np * 2 + tt], av[mt],
                                bv[2 * tt], bv[2 * tt + 1]);
                    }
                }
            }
        }
        __syncthreads();
    }

    // ---- epilogue: acc + bias -> fp16 C ----
    #pragma unroll
    for (int mt = 0; mt < 2; mt++) {
        const int r0 = rowBase + wm * 32 + mt * 16 + (lane >> 2);
        #pragma unroll
        for (int nt = 0; nt < 8; nt++) {
            const int cg = colW + wn * 64 + nt * 8 + (lane & 3) * 2;
            const float2 bv = __ldg((const float2*)&bias[cg]);
            if (r0 < M) {
                __half2 hv = __floats2half2_rn(acc[mt][nt][0] + bv.x,
                                               acc[mt][nt][1] + bv.y);
                *(__half2*)&C[(size_t)r0 * HDIM + cg] = hv;
            }
            if (r0 + 8 < M) {
                __half2 hv = __floats2half2_rn(acc[mt][nt][2] + bv.x,
                                               acc[mt][nt][3] + bv.y);
                *(__half2*)&C[(size_t)(r0 + 8) * HDIM + cg] = hv;
            }
        }
    }
}

// ---------------- CSR build ----------------
__global__ void deg_kernel(const int* __restrict__ ei, int* __restrict__ deg) {
    int e = blockIdx.x * blockDim.x + threadIdx.x;
    if (e < EE) atomicAdd(&deg[ei[EE + e]], 1);
}

__global__ void scan_block_kernel(const int* __restrict__ deg,
                                  int* __restrict__ excl,
                                  int* __restrict__ partial) {
    __shared__ int tsum[256];
    const int base = blockIdx.x * 1024;
    const int idx0 = base + threadIdx.x * 4;
    int v[4], pre[4];
    #pragma unroll
    for (int j = 0; j < 4; j++) v[j] = (idx0 + j < NN) ? deg[idx0 + j] : 0;
    int run = 0;
    #pragma unroll
    for (int j = 0; j < 4; j++) { pre[j] = run; run += v[j]; }
    tsum[threadIdx.x] = run;
    __syncthreads();
    #pragma unroll
    for (int off = 1; off < 256; off <<= 1) {
        int tv = (threadIdx.x >= off) ? tsum[threadIdx.x - off] : 0;
        __syncthreads();
        tsum[threadIdx.x] += tv;
        __syncthreads();
    }
    const int tOff = (threadIdx.x > 0) ? tsum[threadIdx.x - 1] : 0;
    #pragma unroll
    for (int j = 0; j < 4; j++)
        if (idx0 + j < NN) excl[idx0 + j] = tOff + pre[j];
    if (threadIdx.x == 255) partial[blockIdx.x] = tsum[255];
}

__global__ void scan_partial_kernel(int* __restrict__ partial) {
    if (threadIdx.x == 0) {
        int run = 0;
        for (int i = 0; i < NB_SCAN; i++) { int t = partial[i]; partial[i] = run; run += t; }
    }
}

__global__ void add_offset_kernel(int* __restrict__ rowptr, const int* __restrict__ partial) {
    int i = blockIdx.x * blockDim.x + threadIdx.x;
    if (i < NN) rowptr[i] += partial[i >> 10];
    if (i == 0) rowptr[NN] = EE;
}

__global__ void scatter_kernel(const int* __restrict__ ei,
                               const int* __restrict__ rowptr,
                               int* __restrict__ fill,
                               int* __restrict__ col) {
    int e = blockIdx.x * blockDim.x + threadIdx.x;
    if (e >= EE) return;
    const int dst = ei[EE + e];
    const int p = atomicAdd(&fill[dst], 1);
    col[rowptr[dst] + p] = ei[e];
}

// ---------------- node-major fused GATv2 aggregation (fp16 inputs) ----------------
// OUTF16: write fp16 (layer 1 -> GEMM-2 input); else fp32 (layer 2 -> pool).
template <bool SILU, bool OUTF16>
__global__ void node_aggr_kernel(const int* __restrict__ rowptr,
                                 const int* __restrict__ col,
                                 const __half* __restrict__ xl,
                                 const __half* __restrict__ xr,
                                 const float* __restrict__ att,
                                 const float* __restrict__ bias,
                                 float* __restrict__ hout,
                                 __half* __restrict__ hout16) {
    const int node = (blockIdx.x * blockDim.x + threadIdx.x) >> 5;
    const int lane = threadIdx.x & 31;
    if (node >= NN) return;

    const uint2* __restrict__ xd = (const uint2*)(xr + (size_t)node * HDIM);
    const float4 r0 = h4f(xd[lane]);
    const float4 r1 = h4f(xd[lane + 32]);
    const float4 a0 = __ldg(&((const float4*)att)[lane]);
    const float4 a1 = __ldg(&((const float4*)att)[lane + 32]);

    float4 acc0 = make_float4(0.f, 0.f, 0.f, 0.f);
    float4 acc1 = make_float4(0.f, 0.f, 0.f, 0.f);
    float denL = 0.f, denH = 0.f;

    const int pBeg = rowptr[node];
    const int pEnd = rowptr[node + 1];

    uint2 p0n, p1n;
    if (pBeg < pEnd) {
        const uint2* xs = (const uint2*)(xl + (size_t)col[pBeg] * HDIM);
        p0n = xs[lane];
        p1n = xs[lane + 32];
    }

    for (int p = pBeg; p < pEnd; p++) {
        const float4 l0 = h4f(p0n);
        const float4 l1 = h4f(p1n);
        if (p + 1 < pEnd) {                     // prefetch next src row
            const uint2* xs = (const uint2*)(xl + (size_t)col[p + 1] * HDIM);
            p0n = xs[lane];
            p1n = xs[lane + 32];
        }

        float4 s0, s1;
        s0.x = l0.x + r0.x; s0.y = l0.y + r0.y; s0.z = l0.z + r0.z; s0.w = l0.w + r0.w;
        s1.x = l1.x + r1.x; s1.y = l1.y + r1.y; s1.z = l1.z + r1.z; s1.w = l1.w + r1.w;
        s0.x = s0.x > 0.f ? s0.x : 0.2f * s0.x;
        s0.y = s0.y > 0.f ? s0.y : 0.2f * s0.y;
        s0.z = s0.z > 0.f ? s0.z : 0.2f * s0.z;
        s0.w = s0.w > 0.f ? s0.w : 0.2f * s0.w;
        s1.x = s1.x > 0.f ? s1.x : 0.2f * s1.x;
        s1.y = s1.y > 0.f ? s1.y : 0.2f * s1.y;
        s1.z = s1.z > 0.f ? s1.z : 0.2f * s1.z;
        s1.w = s1.w > 0.f ? s1.w : 0.2f * s1.w;

        float q0 = s0.x * a0.x + s0.y * a0.y + s0.z * a0.z + s0.w * a0.w;
        float q1 = s1.x * a1.x + s1.y * a1.y + s1.z * a1.z + s1.w * a1.w;
        #pragma unroll
        for (int o = 8; o > 0; o >>= 1) {       // reduce within 16-lane group
            q0 += __shfl_xor_sync(0xFFFFFFFFu, q0, o);
            q1 += __shfl_xor_sync(0xFFFFFFFFu, q1, o);
        }
        // group g = lane>>4: q0 = score(head g), q1 = score(head 2+g)
        const float eL = __expf(q0);
        const float eH = __expf(q1);

        acc0.x = fmaf(l0.x, eL, acc0.x); acc0.y = fmaf(l0.y, eL, acc0.y);
        acc0.z = fmaf(l0.z, eL, acc0.z); acc0.w = fmaf(l0.w, eL, acc0.w);
        acc1.x = fmaf(l1.x, eH, acc1.x); acc1.y = fmaf(l1.y, eH, acc1.y);
        acc1.z = fmaf(l1.z, eH, acc1.z); acc1.w = fmaf(l1.w, eH, acc1.w);
        denL += eL;
        denH += eH;
    }

    const float invL = 1.0f / (denL + 1e-16f);
    const float invH = 1.0f / (denH + 1e-16f);
    const float4 b0 = __ldg(&((const float4*)bias)[lane]);
    const float4 b1 = __ldg(&((const float4*)bias)[lane + 32]);

    float4 o0, o1;
    o0.x = acc0.x * invL + b0.x; o0.y = acc0.y * invL + b0.y;
    o0.z = acc0.z * invL + b0.z; o0.w = acc0.w * invL + b0.w;
    o1.x = acc1.x * invH + b1.x; o1.y = acc1.y * invH + b1.y;
    o1.z = acc1.z * invH + b1.z; o1.w = acc1.w * invH + b1.w;
    if (SILU) {
        o0.x = o0.x / (1.0f + __expf(-o0.x));
        o0.y = o0.y / (1.0f + __expf(-o0.y));
        o0.z = o0.z / (1.0f + __expf(-o0.z));
        o0.w = o0.w / (1.0f + __expf(-o0.w));
        o1.x = o1.x / (1.0f + __expf(-o1.x));
        o1.y = o1.y / (1.0f + __expf(-o1.y));
        o1.z = o1.z / (1.0f + __expf(-o1.z));
        o1.w = o1.w / (1.0f + __expf(-o1.w));
    }
    if (OUTF16) {
        uint2* ho = (uint2*)(hout16 + (size_t)node * HDIM);
        ho[lane]      = f4_to_h4(o0);
        ho[lane + 32] = f4_to_h4(o1);
    } else {
        float4* ho = (float4*)(hout + (size_t)node * HDIM);
        ho[lane]      = o0;
        ho[lane + 32] = o1;
    }
}

// ---------------- global mean pool (batch is SORTED) ----------------
__global__ void pool_sorted_kernel(const float* __restrict__ h,
                                   const int* __restrict__ batch,
                                   float* __restrict__ out,
                                   float* __restrict__ cnt) {
    __shared__ int sg[256];
    const int t = threadIdx.x;
    const int n0 = blockIdx.x * 256;
    const int n1 = min(n0 + 256, NN);
    if (n0 + t < NN) sg[t] = batch[n0 + t];
    __syncthreads();

    float acc = 0.0f;
    int curG = sg[0];
    int cntLocal = 0;
    for (int n = n0; n < n1; n++) {
        const int g = sg[n - n0];
        if (g != curG) {
            atomicAdd(&out[curG * HDIM + t], acc);
            if (t == 0) atomicAdd(&cnt[curG], (float)cntLocal);
            acc = 0.0f;
            cntLocal = 0;
            curG = g;
        }
        acc += h[(size_t)n * HDIM + t];
        cntLocal++;
    }
    atomicAdd(&out[curG * HDIM + t], acc);
    if (t == 0) atomicAdd(&cnt[curG], (float)cntLocal);
}

__global__ void pool_div_kernel(float* __restrict__ out, const float* __restrict__ cnt) {
    int i = blockIdx.x * blockDim.x + threadIdx.x;
    if (i < GG * HDIM) out[i] = out[i] / fmaxf(cnt[i >> 8], 1.0f);
}

// ---------------- launch ----------------
extern "C" void kernel_launch(void* const* d_in, const int* in_sizes, int n_in,
                              void* d_out, int out_size) {
    const float* x     = (const float*)d_in[0];
    const int*   ei    = (const int*)  d_in[1];
    const int*   batch = (const int*)  d_in[2];
    const float* Wl1   = (const float*)d_in[3];
    const float* bl1   = (const float*)d_in[4];
    const float* Wr1   = (const float*)d_in[5];
    const float* br1   = (const float*)d_in[6];
    const float* att1  = (const float*)d_in[7];
    const float* bias1 = (const float*)d_in[8];
    const float* Wl2   = (const float*)d_in[9];
    const float* bl2   = (const float*)d_in[10];
    const float* Wr2   = (const float*)d_in[11];
    const float* br2   = (const float*)d_in[12];
    const float* att2  = (const float*)d_in[13];
    const float* bias2 = (const float*)d_in[14];
    float* out = (float*)d_out;

    __half *xl, *xr, *h1;
    float *h2, *cnt;
    int *deg, *fill, *rowptr, *colA, *partial;
    cudaGetSymbolAddress((void**)&xl,      g_xl);
    cudaGetSymbolAddress((void**)&xr,      g_xr);
    cudaGetSymbolAddress((void**)&h1,      g_h1);
    cudaGetSymbolAddress((void**)&h2,      g_h2);
    cudaGetSymbolAddress((void**)&cnt,     g_cnt);
    cudaGetSymbolAddress((void**)&deg,     g_deg);
    cudaGetSymbolAddress((void**)&fill,    g_fill);
    cudaGetSymbolAddress((void**)&rowptr,  g_rowptr);
    cudaGetSymbolAddress((void**)&colA,    g_col);
    cudaGetSymbolAddress((void**)&partial, g_partial);

    const dim3 ggrid(4, (NN + 127) / 128);
    const int ebE = (EE + 255) / 256;
    const int nwb = (NN * 32 + 255) / 256;

    // ---- CSR build (used by both layers) ----
    cudaMemsetAsync(deg, 0, NN * sizeof(int));
    cudaMemsetAsync(fill, 0, NN * sizeof(int));
    deg_kernel<<<ebE, 256>>>(ei, deg);
    scan_block_kernel<<<NB_SCAN, 256>>>(deg, rowptr, partial);
    scan_partial_kernel<<<1, 32>>>(partial);
    add_offset_kernel<<<(NN + 255) / 256, 256>>>(rowptr, partial);
    scatter_kernel<<<ebE, 256>>>(ei, rowptr, fill, colA);

    // ---- layer 1 (A = x fp32) ----
    gemm_f16_kernel<false><<<ggrid, 256>>>(x, nullptr, Wl1, Wr1, bl1, br1,
                                           xl, xr, NN, 128);
    node_aggr_kernel<true, true><<<nwb, 256>>>(rowptr, colA, xl, xr, att1, bias1,
                                               nullptr, h1);

    // ---- layer 2 (A = h1 fp16) ----
    gemm_f16_kernel<true><<<ggrid, 256>>>(nullptr, h1, Wl2, Wr2, bl2, br2,
                                          xl, xr, NN, 256);
    node_aggr_kernel<false, false><<<nwb, 256>>>(rowptr, colA, xl, xr, att2, bias2,
                                                 h2, nullptr);

    // ---- global mean pool (sorted batch) ----
    cudaMemsetAsync(out, 0, (size_t)GG * HDIM * sizeof(float));
    cudaMemsetAsync(cnt, 0, (size_t)GG * sizeof(float));
    pool_sorted_kernel<<<(NN + 255) / 256, 256>>>(h2, batch, out, cnt);
    pool_div_kernel<<<(GG * HDIM + 255) / 256, 256>>>(out, cnt);
}